// round 17
// baseline (speedup 1.0000x reference)
#include <cuda_runtime.h>

#define D 128
#define Hh 256
#define T_TBL 384
#define DMAXF 12.0f
#define MAXE 524288
#define MAXN 16384

typedef unsigned long long ull;

// ---------------- scratch (no allocs allowed; 16B-aligned) ----------------
// NOTE: g_cnt must be zero at entry to k_table. First call: CUDA zero-inits
// __device__ globals. Every subsequent call: k_scan re-zeros it after reading.
__device__ __align__(16) float g_filt[T_TBL * D];      // filter table (fp32)
__device__ __align__(16) int   g_cnt[MAXN];
__device__ __align__(16) int   g_off[MAXN + 4];
__device__ __align__(16) int   g_rank[MAXE];           // within-row rank of each edge
__device__ __align__(16) int2  g_edge[MAXE];           // {col, float_bits(tcoord)} bucketed
__device__ __align__(16) float g_agg[MAXN * D];

// ---------------- helpers ----------------
__device__ __forceinline__ ull pack2(float x, float y) {
    ull r; asm("mov.b64 %0, {%1,%2};" : "=l"(r) : "f"(x), "f"(y)); return r;
}
__device__ __forceinline__ void unpack2(ull v, float& x, float& y) {
    asm("mov.b64 {%0,%1}, %2;" : "=f"(x), "=f"(y) : "l"(v));
}
__device__ __forceinline__ void ffma2(ull& c, ull a, ull b) {
    asm("fma.rn.f32x2 %0, %1, %2, %0;" : "+l"(c) : "l"(a), "l"(b));
}
__device__ __forceinline__ float silu_f(float z) {
    return z / (1.f + __expf(-z));
}

// ---------------- K1: filter table + edge count/rank (merged; g_cnt pre-zeroed) ----
__global__ void k_table(const float* __restrict__ W1, const float* __restrict__ b1,
                        const float* __restrict__ W2, const float* __restrict__ b2,
                        const int* __restrict__ ei, int E, int nn) {
    __shared__ float hid[Hh];
    const int t = blockIdx.x, tid = threadIdx.x;   // 384 blocks x 128 threads
    const float dist = t * (DMAXF / (float)(T_TBL - 1));
    for (int j = tid; j < Hh; j += 128) hid[j] = silu_f(dist * W1[j] + b1[j]);
    __syncthreads();
    float s = b2[tid];
#pragma unroll 8
    for (int j = 0; j < Hh; ++j) s += hid[j] * W2[j * D + tid];
    g_filt[t * D + tid] = s;

    // ---- count part: grid-stride, 8 edges per iteration ----
    const int gthreads = gridDim.x * blockDim.x;       // 49152
    for (int e = (t * 128 + tid) * 8; e < E; e += gthreads * 8) {
        if (e + 7 < E) {
            int4 v0 = *(const int4*)(ei + e);
            int4 v1 = *(const int4*)(ei + e + 4);
            unsigned r[8] = {(unsigned)v0.x, (unsigned)v0.y, (unsigned)v0.z, (unsigned)v0.w,
                             (unsigned)v1.x, (unsigned)v1.y, (unsigned)v1.z, (unsigned)v1.w};
            int k[8];
#pragma unroll
            for (int j = 0; j < 8; ++j) {
                if (r[j] >= (unsigned)nn) r[j] = 0;
                k[j] = atomicAdd(&g_cnt[r[j]], 1);
            }
            *(int4*)(g_rank + e) = make_int4(k[0], k[1], k[2], k[3]);
            *(int4*)(g_rank + e + 4) = make_int4(k[4], k[5], k[6], k[7]);
        } else {
            for (int q = e; q < E; ++q) {
                unsigned r = (unsigned)ei[q];
                if (r >= (unsigned)nn) r = 0;
                g_rank[q] = atomicAdd(&g_cnt[r], 1);
            }
        }
    }
}

// ---------------- K2: exclusive scan of MAXN counts (int4); re-zero counts ---------
__global__ void k_scan(int Etot) {
    __shared__ int wsum[32];
    const int tid = threadIdx.x;
    const int lane = tid & 31, wid = tid >> 5;
    const int b0 = tid * 16;
    int4 cv[4];
    int4* cp = (int4*)(g_cnt + b0);
#pragma unroll
    for (int q = 0; q < 4; ++q) cv[q] = cp[q];
    // re-zero own range for the NEXT kernel_launch invocation (thread-private, safe)
    const int4 z4 = make_int4(0, 0, 0, 0);
#pragma unroll
    for (int q = 0; q < 4; ++q) cp[q] = z4;

    int vals[16];
    int s = 0;
#pragma unroll
    for (int q = 0; q < 4; ++q) {
        vals[q * 4 + 0] = s; s += cv[q].x;
        vals[q * 4 + 1] = s; s += cv[q].y;
        vals[q * 4 + 2] = s; s += cv[q].z;
        vals[q * 4 + 3] = s; s += cv[q].w;
    }
    int inc = s;
#pragma unroll
    for (int d = 1; d < 32; d <<= 1) {
        int o = __shfl_up_sync(0xffffffffu, inc, d);
        if (lane >= d) inc += o;
    }
    if (lane == 31) wsum[wid] = inc;
    __syncthreads();
    if (wid == 0) {
        int v = wsum[lane];
#pragma unroll
        for (int d = 1; d < 32; d <<= 1) {
            int o = __shfl_up_sync(0xffffffffu, v, d);
            if (lane >= d) v += o;
        }
        wsum[lane] = v;
    }
    __syncthreads();
    const int base = (inc - s) + (wid ? wsum[wid - 1] : 0);
    int4* op = (int4*)(g_off + b0);
#pragma unroll
    for (int q = 0; q < 4; ++q) {
        int4 o;
        o.x = base + vals[q * 4 + 0];
        o.y = base + vals[q * 4 + 1];
        o.z = base + vals[q * 4 + 2];
        o.w = base + vals[q * 4 + 3];
        op[q] = o;
    }
    if (tid == 1023) g_off[MAXN] = Etot;
}

// ---------------- K3: atomic-free bucket scatter (4 edges/thread ILP) --------------
__global__ void k_scatter(const int* __restrict__ ei, const float* __restrict__ x,
                          int E, int nn) {
    const int e0 = (blockIdx.x * blockDim.x + threadIdx.x) * 4;
    if (e0 >= E) return;

    if (e0 + 3 < E) {
        int4 rv = *(const int4*)(ei + e0);
        int4 cvv = *(const int4*)(ei + E + e0);
        int4 rk = *(const int4*)(g_rank + e0);
        unsigned r[4] = {(unsigned)rv.x, (unsigned)rv.y, (unsigned)rv.z, (unsigned)rv.w};
        unsigned c[4] = {(unsigned)cvv.x, (unsigned)cvv.y, (unsigned)cvv.z, (unsigned)cvv.w};
        int rkv[4] = {rk.x, rk.y, rk.z, rk.w};
#pragma unroll
        for (int j = 0; j < 4; ++j) {
            if (r[j] >= (unsigned)nn) r[j] = 0;
            if (c[j] >= (unsigned)nn) c[j] = 0;
        }
        int off[4];
#pragma unroll
        for (int j = 0; j < 4; ++j) off[j] = g_off[r[j]];
        float rx[4], ry[4], rz[4], cx[4], cy[4], cz[4];
#pragma unroll
        for (int j = 0; j < 4; ++j) {
            rx[j] = __ldg(x + r[j] * 3 + 0);
            ry[j] = __ldg(x + r[j] * 3 + 1);
            rz[j] = __ldg(x + r[j] * 3 + 2);
            cx[j] = __ldg(x + c[j] * 3 + 0);
            cy[j] = __ldg(x + c[j] * 3 + 1);
            cz[j] = __ldg(x + c[j] * 3 + 2);
        }
#pragma unroll
        for (int j = 0; j < 4; ++j) {
            const float dx = rx[j] - cx[j], dy = ry[j] - cy[j], dz = rz[j] - cz[j];
            const float dist = sqrtf(dx * dx + dy * dy + dz * dz);
            const float tt = (dist <= DMAXF) ? dist * ((float)(T_TBL - 1) / DMAXF) : -dist;
            int2 o; o.x = (int)c[j]; o.y = __float_as_int(tt);
            g_edge[off[j] + rkv[j]] = o;
        }
    } else {
        for (int e = e0; e < E; ++e) {
            unsigned r = (unsigned)ei[e];
            unsigned c = (unsigned)ei[E + e];
            if (r >= (unsigned)nn) r = 0;
            if (c >= (unsigned)nn) c = 0;
            const int pos = g_off[r] + g_rank[e];
            const float dx = x[r * 3 + 0] - x[c * 3 + 0];
            const float dy = x[r * 3 + 1] - x[c * 3 + 1];
            const float dz = x[r * 3 + 2] - x[c * 3 + 2];
            const float dist = sqrtf(dx * dx + dy * dy + dz * dz);
            const float tt = (dist <= DMAXF) ? dist * ((float)(T_TBL - 1) / DMAXF) : -dist;
            int2 o; o.x = (int)c; o.y = __float_as_int(tt);
            g_edge[pos] = o;
        }
    }
}

// ---------------- K4: aggregate (warp/node; table in SMEM; MLP=8; 768 thr) ---------
__global__ __launch_bounds__(768, 1)
void k_agg(const float* __restrict__ h,
           const float* __restrict__ W1, const float* __restrict__ b1,
           const float* __restrict__ W2, const float* __restrict__ b2, int nn) {
    extern __shared__ float tbl[];   // [T_TBL][D]
    for (int i = threadIdx.x; i < T_TBL * D / 4; i += blockDim.x)
        ((float4*)tbl)[i] = ((const float4*)g_filt)[i];
    __syncthreads();

    const int lane = threadIdx.x & 31;
    const int gw = (blockIdx.x * blockDim.x + threadIdx.x) >> 5;
    const int nwarps = (gridDim.x * blockDim.x) >> 5;
    const int d0 = lane * 4;

    for (int v = gw; v < nn; v += nwarps) {
        const int beg = g_off[v], end = g_off[v + 1];
        float ax = 0.f, ay = 0.f, az = 0.f, aw = 0.f;

        // prefetched edge descriptor for the upcoming 8-edge round (lanes 0..7)
        int2 ed = make_int2(0, 0);
        if (lane < 8 && beg + lane < end) ed = g_edge[beg + lane];

        int e0 = beg;
        for (; e0 + 8 <= end; e0 += 8) {
            const int2 cur = ed;
            if (lane < 8 && e0 + 8 + lane < end) ed = g_edge[e0 + 8 + lane];

            float4 hb[8];
            float  tc[8];
#pragma unroll
            for (int j = 0; j < 8; ++j) {
                const int c = __shfl_sync(0xffffffffu, cur.x, j);
                tc[j] = __int_as_float(__shfl_sync(0xffffffffu, cur.y, j));
                hb[j] = *(const float4*)(h + c * D + d0);
            }
#pragma unroll
            for (int j = 0; j < 8; ++j) {
                const float t = tc[j];
                float fx, fy, fz, fw;
                if (t >= 0.f) {
                    int i0 = (int)t; i0 = min(i0, T_TBL - 2);
                    const float fr = t - (float)i0;
                    const float4 fa = *(const float4*)(tbl + i0 * D + d0);
                    const float4 fb = *(const float4*)(tbl + (i0 + 1) * D + d0);
                    fx = fa.x + fr * (fb.x - fa.x);
                    fy = fa.y + fr * (fb.y - fa.y);
                    fz = fa.z + fr * (fb.z - fa.z);
                    fw = fa.w + fr * (fb.w - fa.w);
                } else {
                    const float dist = -t;   // exact fallback (dist > DMAXF), ~never taken
                    fx = b2[d0]; fy = b2[d0 + 1]; fz = b2[d0 + 2]; fw = b2[d0 + 3];
                    for (int q = 0; q < Hh; ++q) {
                        float hv = silu_f(dist * W1[q] + b1[q]);
                        fx += hv * W2[q * D + d0];
                        fy += hv * W2[q * D + d0 + 1];
                        fz += hv * W2[q * D + d0 + 2];
                        fw += hv * W2[q * D + d0 + 3];
                    }
                }
                ax += hb[j].x * fx; ay += hb[j].y * fy;
                az += hb[j].z * fz; aw += hb[j].w * fw;
            }
        }
        // tail
        for (; e0 < end; ++e0) {
            const int2 e2 = g_edge[e0];
            const int c = e2.x;
            const float t = __int_as_float(e2.y);
            const float4 h4 = *(const float4*)(h + c * D + d0);
            float fx, fy, fz, fw;
            if (t >= 0.f) {
                int i0 = (int)t; i0 = min(i0, T_TBL - 2);
                const float fr = t - (float)i0;
                const float4 fa = *(const float4*)(tbl + i0 * D + d0);
                const float4 fb = *(const float4*)(tbl + (i0 + 1) * D + d0);
                fx = fa.x + fr * (fb.x - fa.x);
                fy = fa.y + fr * (fb.y - fa.y);
                fz = fa.z + fr * (fb.z - fa.z);
                fw = fa.w + fr * (fb.w - fa.w);
            } else {
                const float dist = -t;
                fx = b2[d0]; fy = b2[d0 + 1]; fz = b2[d0 + 2]; fw = b2[d0 + 3];
                for (int q = 0; q < Hh; ++q) {
                    float hv = silu_f(dist * W1[q] + b1[q]);
                    fx += hv * W2[q * D + d0];
                    fy += hv * W2[q * D + d0 + 1];
                    fz += hv * W2[q * D + d0 + 2];
                    fw += hv * W2[q * D + d0 + 3];
                }
            }
            ax += h4.x * fx; ay += h4.y * fy; az += h4.z * fz; aw += h4.w * fw;
        }

        const float inv = 1.f / fmaxf((float)(end - beg), 1.f);
        float4 o; o.x = ax * inv; o.y = ay * inv; o.z = az * inv; o.w = aw * inv;
        *(float4*)(g_agg + v * D + d0) = o;
    }
}

// ---------------- K5: fused node MLP: [h|agg]@W3 + b3 -> LN -> SiLU -> @W4 + b4 ----
// block = 32 nodes, 256 threads. thread(tx,ty): nodes ty*4+j, GEMM1 cols tx*8..+7 (4 f32x2 pairs)
#define SM_IN_STRIDE 260
__global__ __launch_bounds__(256, 2)
void k_mlp(const float* __restrict__ h,
           const float* __restrict__ W3, const float* __restrict__ b3,
           const float* __restrict__ gam, const float* __restrict__ bet,
           const float* __restrict__ W4, const float* __restrict__ b4,
           float* __restrict__ out, int nn) {
    extern __shared__ float sm[];
    float* in_s = sm;                    // [32][260]
    float* wt = sm + 32 * SM_IN_STRIDE;  // [2][4096] W3 tiles (reused [2][2048] for W4)

    const int tid = threadIdx.x;
    const int tx = tid & 31, ty = tid >> 5;
    const int node0 = blockIdx.x * 32;

    // load input tile [h | agg] -> in_s[node][k]
    {
        const int n = tid >> 3, seg = tid & 7;
        const int gn = min(node0 + n, nn - 1);
        const float* src = (seg < 4) ? (h + gn * D + seg * 32)
                                     : (g_agg + gn * D + (seg - 4) * 32);
        float* dst = in_s + n * SM_IN_STRIDE + seg * 32;
#pragma unroll
        for (int i = 0; i < 8; ++i) ((float4*)dst)[i] = ((const float4*)src)[i];
    }

    // preload W3 tile 0
    float4 pre[4];
#pragma unroll
    for (int i = 0; i < 4; ++i) pre[i] = ((const float4*)W3)[tid + i * 256];
#pragma unroll
    for (int i = 0; i < 4; ++i) ((float4*)wt)[tid + i * 256] = pre[i];
    __syncthreads();

    ull acc[4][4];
#pragma unroll
    for (int j = 0; j < 4; ++j)
#pragma unroll
        for (int p = 0; p < 4; ++p) acc[j][p] = 0ull;

    const float* r0 = in_s + (ty * 4 + 0) * SM_IN_STRIDE;
    const float* r1 = in_s + (ty * 4 + 1) * SM_IN_STRIDE;
    const float* r2 = in_s + (ty * 4 + 2) * SM_IN_STRIDE;
    const float* r3 = in_s + (ty * 4 + 3) * SM_IN_STRIDE;

#pragma unroll 1
    for (int t = 0; t < 16; ++t) {
        float* cur = wt + (t & 1) * 4096;
        float* nxt = wt + ((t + 1) & 1) * 4096;
        if (t < 15) {
            const float4* gs = (const float4*)(W3 + (t + 1) * 4096);
#pragma unroll
            for (int i = 0; i < 4; ++i) pre[i] = gs[tid + i * 256];
        }
#pragma unroll
        for (int kk = 0; kk < 16; ++kk) {
            const int k = t * 16 + kk;
            const ull a0 = pack2(r0[k], r0[k]);
            const ull a1 = pack2(r1[k], r1[k]);
            const ull a2 = pack2(r2[k], r2[k]);
            const ull a3 = pack2(r3[k], r3[k]);
            const ull* br = (const ull*)(cur + kk * 256 + tx * 8);
            const ull b0 = br[0], b1v = br[1], b2v = br[2], b3v = br[3];
            ffma2(acc[0][0], a0, b0); ffma2(acc[0][1], a0, b1v); ffma2(acc[0][2], a0, b2v); ffma2(acc[0][3], a0, b3v);
            ffma2(acc[1][0], a1, b0); ffma2(acc[1][1], a1, b1v); ffma2(acc[1][2], a1, b2v); ffma2(acc[1][3], a1, b3v);
            ffma2(acc[2][0], a2, b0); ffma2(acc[2][1], a2, b1v); ffma2(acc[2][2], a2, b2v); ffma2(acc[2][3], a2, b3v);
            ffma2(acc[3][0], a3, b0); ffma2(acc[3][1], a3, b1v); ffma2(acc[3][2], a3, b2v); ffma2(acc[3][3], a3, b3v);
        }
        if (t < 15) {
#pragma unroll
            for (int i = 0; i < 4; ++i) ((float4*)nxt)[tid + i * 256] = pre[i];
            __syncthreads();
        }
    }

    // bias + LayerNorm + SiLU, write back into in_s (rows are warp-private)
    float2 u[4][4];
    {
        const float4 bbl = *(const float4*)(b3 + tx * 8);
        const float4 bbh = *(const float4*)(b3 + tx * 8 + 4);
        const float bv[8] = {bbl.x, bbl.y, bbl.z, bbl.w, bbh.x, bbh.y, bbh.z, bbh.w};
#pragma unroll
        for (int j = 0; j < 4; ++j)
#pragma unroll
            for (int p = 0; p < 4; ++p) {
                unpack2(acc[j][p], u[j][p].x, u[j][p].y);
                u[j][p].x += bv[2 * p]; u[j][p].y += bv[2 * p + 1];
            }
    }
    {
        const float4 g0 = *(const float4*)(gam + tx * 8);
        const float4 g1 = *(const float4*)(gam + tx * 8 + 4);
        const float4 e0 = *(const float4*)(bet + tx * 8);
        const float4 e1 = *(const float4*)(bet + tx * 8 + 4);
        const float gv[8] = {g0.x, g0.y, g0.z, g0.w, g1.x, g1.y, g1.z, g1.w};
        const float ev[8] = {e0.x, e0.y, e0.z, e0.w, e1.x, e1.y, e1.z, e1.w};
#pragma unroll
        for (int j = 0; j < 4; ++j) {
            float s = 0.f, q = 0.f;
#pragma unroll
            for (int p = 0; p < 4; ++p) {
                s += u[j][p].x + u[j][p].y;
                q += u[j][p].x * u[j][p].x + u[j][p].y * u[j][p].y;
            }
#pragma unroll
            for (int dsh = 16; dsh; dsh >>= 1) {
                s += __shfl_xor_sync(0xffffffffu, s, dsh);
                q += __shfl_xor_sync(0xffffffffu, q, dsh);
            }
            const float mu = s * (1.f / 256.f);
            const float var = q * (1.f / 256.f) - mu * mu;
            const float rs = rsqrtf(var + 1e-5f);
            float* urow = in_s + (ty * 4 + j) * SM_IN_STRIDE + tx * 8;
#pragma unroll
            for (int p = 0; p < 4; ++p) {
                const float ux = (u[j][p].x - mu) * rs * gv[2 * p] + ev[2 * p];
                const float uy = (u[j][p].y - mu) * rs * gv[2 * p + 1] + ev[2 * p + 1];
                urow[2 * p] = silu_f(ux);
                urow[2 * p + 1] = silu_f(uy);
            }
        }
    }
    __syncwarp();

    // GEMM2: out = U @ W4 + b4. thread: 4 nodes x 4 cols (2 f32x2 pairs)
    float4 pre2[2];
#pragma unroll
    for (int i = 0; i < 2; ++i) pre2[i] = ((const float4*)W4)[tid + i * 256];
#pragma unroll
    for (int i = 0; i < 2; ++i) ((float4*)wt)[tid + i * 256] = pre2[i];
    __syncthreads();   // also fences stragglers off W3 tile15 / their in_s rows

    ull acc2[4][2];
#pragma unroll
    for (int j = 0; j < 4; ++j) { acc2[j][0] = 0ull; acc2[j][1] = 0ull; }

#pragma unroll 1
    for (int t = 0; t < 16; ++t) {
        float* cur = wt + (t & 1) * 2048;
        float* nxt = wt + ((t + 1) & 1) * 2048;
        if (t < 15) {
            const float4* gs = (const float4*)(W4 + (t + 1) * 2048);
            pre2[0] = gs[tid]; pre2[1] = gs[tid + 256];
        }
#pragma unroll
        for (int kk = 0; kk < 16; ++kk) {
            const int k = t * 16 + kk;
            const ull a0 = pack2(r0[k], r0[k]);
            const ull a1 = pack2(r1[k], r1[k]);
            const ull a2 = pack2(r2[k], r2[k]);
            const ull a3 = pack2(r3[k], r3[k]);
            const ull* br = (const ull*)(cur + kk * 128 + tx * 4);
            const ull b0 = br[0], b1v = br[1];
            ffma2(acc2[0][0], a0, b0); ffma2(acc2[0][1], a0, b1v);
            ffma2(acc2[1][0], a1, b0); ffma2(acc2[1][1], a1, b1v);
            ffma2(acc2[2][0], a2, b0); ffma2(acc2[2][1], a2, b1v);
            ffma2(acc2[3][0], a3, b0); ffma2(acc2[3][1], a3, b1v);
        }
        if (t < 15) {
            ((float4*)nxt)[tid] = pre2[0];
            ((float4*)nxt)[tid + 256] = pre2[1];
            __syncthreads();
        }
    }

    // epilogue
    const float4 b4v = *(const float4*)(b4 + tx * 4);
#pragma unroll
    for (int j = 0; j < 4; ++j) {
        float2 o0, o1;
        unpack2(acc2[j][0], o0.x, o0.y);
        unpack2(acc2[j][1], o1.x, o1.y);
        o0.x += b4v.x; o0.y += b4v.y; o1.x += b4v.z; o1.y += b4v.w;
        const int gn = node0 + ty * 4 + j;
        if (gn < nn) {
            float2* op = (float2*)(out + gn * D + tx * 4);
            op[0] = o0; op[1] = o1;
        }
    }
}

// ---------------- host ----------------
extern "C" void kernel_launch(void* const* d_in, const int* in_sizes, int n_in,
                              void* d_out, int out_size) {
    const float* x = (const float*)d_in[0];
    const float* h = (const float*)d_in[1];
    const int* ei = (const int*)d_in[2];    // edge_indices: int32
    int base = 3;
    if (n_in >= 14 && in_sizes[3] == 1) base = 4;   // batch_size scalar present
    const float* W1 = (const float*)d_in[base + 0];
    const float* b1 = (const float*)d_in[base + 1];
    const float* W2 = (const float*)d_in[base + 2];
    const float* b2 = (const float*)d_in[base + 3];
    const float* W3 = (const float*)d_in[base + 4];
    const float* b3 = (const float*)d_in[base + 5];
    const float* gam = (const float*)d_in[base + 6];
    const float* bet = (const float*)d_in[base + 7];
    const float* W4 = (const float*)d_in[base + 8];
    const float* b4 = (const float*)d_in[base + 9];
    float* out = (float*)d_out;

    int E = in_sizes[2] / 2;
    int nn = in_sizes[1] / D;
    if (E > MAXE) E = MAXE;
    if (nn > MAXN) nn = MAXN;

    const int agg_smem = T_TBL * D * 4;                          // 196608
    const int mlp_smem = (32 * SM_IN_STRIDE + 2 * 4096) * 4;     // 66048
    cudaFuncSetAttribute(k_agg, cudaFuncAttributeMaxDynamicSharedMemorySize, agg_smem);
    cudaFuncSetAttribute(k_mlp, cudaFuncAttributeMaxDynamicSharedMemorySize, mlp_smem);

    const int e4 = (E + 3) / 4;
    k_table<<<T_TBL, 128>>>(W1, b1, W2, b2, ei, E, nn);
    k_scan<<<1, 1024>>>(E);
    k_scatter<<<(e4 + 255) / 256, 256>>>(ei, x, E, nn);
    k_agg<<<148, 768, agg_smem>>>(h, W1, b1, W2, b2, nn);
    k_mlp<<<(nn + 31) / 32, 256, mlp_smem>>>(h, W3, b3, gam, bet, W4, b4, out, nn);
}